// round 16
// baseline (speedup 1.0000x reference)
#include <cuda_runtime.h>
#include <cuda_bf16.h>
#include <cstdint>

#define NN 8192
#define IN_DIM 256
#define HID 128
#define PZ 136  // pitch bf16 for Zn staging (odd 16B stride)
#define PT 72   // pitch bf16 for 64-col Zt tiles (odd 16B stride)
#define NCTA 296           // 148 SMs x 2 CTAs
#define NTILE 16384        // 128 rowblocks(64r) x 128 coltiles(64c)

// smem element offsets (bf16): 3 Zt buffers x (hi,lo); Zn staged in buf0
#define ZT_E(buf, hl) (((buf) * 2 + (hl)) * 128 * PT)
#define SMEM_BYTES (6 * 128 * PT * 2)  // 110592 per CTA -> 2 CTAs/SM

// ---------------- device scratch (no cudaMalloc allowed) -------------------
__device__ __nv_bfloat16 g_Zhi[NN * HID];
__device__ __nv_bfloat16 g_Zlo[NN * HID];
__device__ __nv_bfloat16 g_ZThi[(long)HID * NN];
__device__ __nv_bfloat16 g_ZTlo[(long)HID * NN];
__device__ float g_outp[NN * HID];  // atomically accumulated out partial
__device__ float g_rs[NN];          // atomically accumulated rowsum

// ---------------- primitives (baseline PTX, no sm_103a gating) -------------
__device__ __forceinline__ uint32_t smem_u32(const void* p) {
    uint32_t a;
    asm("{ .reg .u64 t; cvta.to.shared.u64 t, %1; cvt.u32.u64 %0, t; }"
        : "=r"(a) : "l"(p));
    return a;
}
__device__ __forceinline__ void ldsm_x4(uint32_t* r, uint32_t addr) {
    asm volatile("ldmatrix.sync.aligned.m8n8.x4.shared.b16 {%0,%1,%2,%3}, [%4];"
                 : "=r"(r[0]), "=r"(r[1]), "=r"(r[2]), "=r"(r[3]) : "r"(addr));
}
__device__ __forceinline__ void ldsm_x4t(uint32_t* r, uint32_t addr) {
    asm volatile("ldmatrix.sync.aligned.m8n8.x4.trans.shared.b16 {%0,%1,%2,%3}, [%4];"
                 : "=r"(r[0]), "=r"(r[1]), "=r"(r[2]), "=r"(r[3]) : "r"(addr));
}
__device__ __forceinline__ void mma16816(float* c, const uint32_t* a,
                                         const uint32_t* b) {
    asm volatile(
        "mma.sync.aligned.m16n8k16.row.col.f32.bf16.bf16.f32 "
        "{%0,%1,%2,%3}, {%4,%5,%6,%7}, {%8,%9}, {%0,%1,%2,%3};"
        : "+f"(c[0]), "+f"(c[1]), "+f"(c[2]), "+f"(c[3])
        : "r"(a[0]), "r"(a[1]), "r"(a[2]), "r"(a[3]), "r"(b[0]), "r"(b[1]));
}
__device__ __forceinline__ void cp16(uint32_t dst, const void* src) {
    asm volatile("cp.async.cg.shared.global [%0], [%1], 16;"
                 :: "r"(dst), "l"(src));
}
#define CP_COMMIT() asm volatile("cp.async.commit_group;")
#define CP_WAIT1() asm volatile("cp.async.wait_group 1;")
#define CP_WAIT0() asm volatile("cp.async.wait_group 0;")
__device__ __forceinline__ void stcs2(float* p, float x, float y) {
    asm volatile("st.global.cs.v2.f32 [%0], {%1,%2};" :: "l"(p), "f"(x), "f"(y));
}
__device__ __forceinline__ uint32_t pack_bf2(float x, float y) {
    __nv_bfloat162 t;
    t.x = __float2bfloat16(x);
    t.y = __float2bfloat16(y);
    return *reinterpret_cast<uint32_t*>(&t);
}
// hi-pack of truncated bf16 pair: d = [v0.top16, v1.top16]
__device__ __forceinline__ uint32_t prmt7632(uint32_t a, uint32_t b) {
    uint32_t d;
    asm("prmt.b32 %0, %1, %2, 0x7632;" : "=r"(d) : "r"(a), "r"(b));
    return d;
}
// lo-pack: {lower=cvt(l0), upper=cvt(l1)}
__device__ __forceinline__ uint32_t cvt_bf2(float l0, float l1) {
    uint32_t d;
    asm("cvt.rn.bf16x2.f32 %0, %1, %2;" : "=r"(d) : "f"(l1), "f"(l0));
    return d;
}

// ---------------------------------------------------------------------------
// Phase 1: Z = X @ W^T (fp32), emit bf16 hi/lo + smem-staged transposed hi/lo.
// Also zeroes g_outp and g_rs.
// ---------------------------------------------------------------------------
__global__ __launch_bounds__(256) void k_gemm_z(const float* __restrict__ X,
                                                const float* __restrict__ W) {
    __shared__ __align__(16) float pool[2 * 64 * 33];
    float* Xs = pool;
    float* Ws = pool + 64 * 33;
    const int tid = threadIdx.x;
    const int flatb = blockIdx.y * gridDim.x + blockIdx.x;  // 0..255
    {
        float4 z4 = make_float4(0.f, 0.f, 0.f, 0.f);
        float4* op4 = (float4*)g_outp + (flatb * 256 + tid) * 4;
#pragma unroll
        for (int j = 0; j < 4; j++) op4[j] = z4;
        if (flatb < 32) g_rs[flatb * 256 + tid] = 0.0f;
    }
    const int tx = tid & 15, ty = tid >> 4;
    const int row0 = blockIdx.x * 64;
    const int col0 = blockIdx.y * 64;
    float acc[4][4] = {};

    for (int k0 = 0; k0 < IN_DIM; k0 += 32) {
        for (int idx = tid; idx < 64 * 32; idx += 256) {
            int r = idx >> 5, c = idx & 31;
            Xs[r * 33 + c] = X[(row0 + r) * IN_DIM + k0 + c];
            Ws[r * 33 + c] = W[(col0 + r) * IN_DIM + k0 + c];
        }
        __syncthreads();
#pragma unroll 8
        for (int k = 0; k < 32; k++) {
            float a[4], b[4];
#pragma unroll
            for (int i = 0; i < 4; i++) a[i] = Xs[(ty * 4 + i) * 33 + k];
#pragma unroll
            for (int j = 0; j < 4; j++) b[j] = Ws[(tx * 4 + j) * 33 + k];
#pragma unroll
            for (int i = 0; i < 4; i++)
#pragma unroll
                for (int j = 0; j < 4; j++) acc[i][j] = fmaf(a[i], b[j], acc[i][j]);
        }
        __syncthreads();
    }

    __nv_bfloat16 h4[4][4], l4[4][4];
#pragma unroll
    for (int i = 0; i < 4; i++)
#pragma unroll
        for (int j = 0; j < 4; j++) {
            int r = row0 + ty * 4 + i, c = col0 + tx * 4 + j;
            float v = acc[i][j];
            __nv_bfloat16 h = __float2bfloat16(v);
            __nv_bfloat16 l = __float2bfloat16(v - __bfloat162float(h));
            h4[i][j] = h; l4[i][j] = l;
            g_Zhi[r * HID + c] = h;
            g_Zlo[r * HID + c] = l;
        }

    __nv_bfloat16* tb = (__nv_bfloat16*)pool;
#pragma unroll
    for (int pass = 0; pass < 2; pass++) {
        __syncthreads();
#pragma unroll
        for (int i = 0; i < 4; i++)
#pragma unroll
            for (int j = 0; j < 4; j++)
                tb[(tx * 4 + j) * 72 + ty * 4 + i] = pass ? l4[i][j] : h4[i][j];
        __syncthreads();
        __nv_bfloat16* gp = pass ? g_ZTlo : g_ZThi;
#pragma unroll
        for (int k = 0; k < 2; k++) {
            int idx = tid + k * 256;
            int c_loc = idx >> 3;
            int r8 = (idx & 7) * 8;
            *(uint4*)&gp[(long)(col0 + c_loc) * NN + row0 + r8] =
                *(uint4*)&tb[c_loc * 72 + r8];
        }
    }
}

// ---------------------------------------------------------------------------
// issue async copy of one 128x64 Zt tile pair (hi+lo) into buffer buf (0..2)
// 128-thread version.
// ---------------------------------------------------------------------------
__device__ __forceinline__ void issue_zt(uint32_t smb, int buf, int m0, int tid) {
    const __nv_bfloat16* gh = g_ZThi + m0;
    const __nv_bfloat16* gl = g_ZTlo + m0;
    const uint32_t dH = smb + ZT_E(buf, 0) * 2;
    const uint32_t dL = smb + ZT_E(buf, 1) * 2;
#pragma unroll
    for (int i = 0; i < 8; i++) {
        int idx = tid + i * 128;   // 0..1023
        int row = idx >> 3;        // 0..127 (h)
        int c8 = (idx & 7) * 8;    // 0..56 (m)
        uint32_t so = (uint32_t)(row * PT + c8) * 2;
        long go = (long)row * NN + c8;
        cp16(dH + so, gh + go);
        cp16(dL + so, gl + go);
    }
}

// ---------------------------------------------------------------------------
// Phase 2: persistent over 16384 (rowblock64, coltile64) units; 296 CTAs of
// 128 threads (2 CTAs/SM). Register-resident S (FA2): warp owns 16 S-rows x
// 64-col tile. Zn staged through Zt-slot0 then lives in registers only.
// ---------------------------------------------------------------------------
__global__ __launch_bounds__(128, 2) void k_pass2(float* __restrict__ A) {
    extern __shared__ __nv_bfloat16 sm[];
    const uint32_t smb = smem_u32(sm);
    const int tid = threadIdx.x;
    const int wid = tid >> 5, lane = tid & 31;
    const int g = lane >> 2, tq = lane & 3;
    const int l15 = lane & 15;
    const int hi8 = (lane >> 4) * 8;

    int gid = (int)(((long)blockIdx.x * NTILE) / NCTA);
    const int gend = (int)(((long)(blockIdx.x + 1) * NTILE) / NCTA);

    const uint32_t b2off =
        (uint32_t)((((lane & 7) + ((lane >> 4) & 1) * 8) * PT +
                    ((lane >> 3) & 1) * 8) * 2);

    while (gid < gend) {
        const int rb = gid >> 7;
        const int segEnd = min(gend, (rb + 1) << 7);
        const int segLen = segEnd - gid;
        const int n0 = rb << 6;  // 64-row blocks

        __syncthreads();  // prior segment fully done with smem

        // ---- stage Zn (64x128 hi/lo) into Zt slot 0, pitch PZ ----
        {
            const __nv_bfloat16* gh = g_Zhi + (long)n0 * HID;
            const __nv_bfloat16* gl = g_Zlo + (long)n0 * HID;
            __nv_bfloat16* sh = sm + ZT_E(0, 0);
            __nv_bfloat16* sl = sm + ZT_E(0, 1);
#pragma unroll
            for (int i = 0; i < 8; i++) {
                int idx = tid + i * 128;
                int row = idx >> 4;
                int c8 = (idx & 15) * 8;
                *(uint4*)&sh[row * PZ + c8] = *(const uint4*)&gh[(long)row * HID + c8];
                *(uint4*)&sl[row * PZ + c8] = *(const uint4*)&gl[(long)row * HID + c8];
            }
        }
        __syncthreads();

        // resident Zn fragments for this 64-row block
        uint32_t rAH[8][4], rAL[8][4];
        {
            const uint32_t aH = smb + (ZT_E(0, 0) + (wid * 16 + l15) * PZ + hi8) * 2;
            const uint32_t aL = smb + (ZT_E(0, 1) + (wid * 16 + l15) * PZ + hi8) * 2;
#pragma unroll
            for (int k8 = 0; k8 < 8; k8++) {
                ldsm_x4(rAH[k8], aH + (k8 * 16) * 2);
                ldsm_x4(rAL[k8], aL + (k8 * 16) * 2);
            }
        }
        __syncthreads();  // all warps done reading Zn staging

        issue_zt(smb, 0, (gid & 127) * 64, tid);
        CP_COMMIT();
        if (segLen > 1) {
            issue_zt(smb, 1, ((gid + 1) & 127) * 64, tid);
            CP_COMMIT();
        }

        float oacc[16][4] = {};
        float rs0 = 0.0f, rs1 = 0.0f;

        for (int i = 0; i < segLen; i++) {
            const int cur = i % 3;
            const int m0 = ((gid + i) & 127) * 64;
            if (i + 1 < segLen) CP_WAIT1(); else CP_WAIT0();
            __syncthreads();  // Zt[cur] ready; slot (i+2)%3 free
            if (i + 2 < segLen) {
                issue_zt(smb, (i + 2) % 3, ((gid + i + 2) & 127) * 64, tid);
                CP_COMMIT();
            }

            const uint32_t ztH = smb + ZT_E(cur, 0) * 2;
            const uint32_t ztL = smb + ZT_E(cur, 1) * 2;
            const uint32_t b1H = ztH + (uint32_t)(l15 * PT + hi8) * 2;
            const uint32_t b1L = ztL + (uint32_t)(l15 * PT + hi8) * 2;

            // ---- GEMM1: S[16x64] = Zn(split) @ Zt(split) ----
            float cacc[8][4] = {};
#pragma unroll
            for (int k8 = 0; k8 < 8; k8++) {
                uint32_t bH[4][4], bL[4][4];
#pragma unroll
                for (int nc = 0; nc < 4; nc++) {
                    ldsm_x4t(bH[nc], b1H + (uint32_t)(k8 * 16 * PT + nc * 16) * 2);
                    ldsm_x4t(bL[nc], b1L + (uint32_t)(k8 * 16 * PT + nc * 16) * 2);
                }
#pragma unroll
                for (int nc = 0; nc < 4; nc++) {
                    mma16816(cacc[2 * nc], rAH[k8], &bH[nc][0]);
                    mma16816(cacc[2 * nc + 1], rAH[k8], &bH[nc][2]);
                    mma16816(cacc[2 * nc], rAH[k8], &bL[nc][0]);
                    mma16816(cacc[2 * nc + 1], rAH[k8], &bL[nc][2]);
                    mma16816(cacc[2 * nc], rAL[k8], &bH[nc][0]);
                    mma16816(cacc[2 * nc + 1], rAL[k8], &bH[nc][2]);
                }
            }

            // ---- epilogue: relu, rowsum, A store, cheap trunc-split pack ----
            uint32_t aSH[4][4], aSL[4][4];
#pragma unroll
            for (int nf = 0; nf < 8; nf++) {
                float* c = cacc[nf];
                float v0 = fmaxf(c[0], 0.f), v1 = fmaxf(c[1], 0.f);
                float v2 = fmaxf(c[2], 0.f), v3 = fmaxf(c[3], 0.f);
                rs0 += v0 + v1;
                rs1 += v2 + v3;
                const int lr = wid * 16 + g;
                const int lc = nf * 8 + 2 * tq;
                stcs2(&A[(long)(n0 + lr) * NN + m0 + lc], v0, v1);
                stcs2(&A[(long)(n0 + lr + 8) * NN + m0 + lc], v2, v3);
                uint32_t u0 = __float_as_uint(v0), u1 = __float_as_uint(v1);
                uint32_t u2 = __float_as_uint(v2), u3 = __float_as_uint(v3);
                const int j = nf >> 1, half = (nf & 1) * 2;
                aSH[j][half + 0] = prmt7632(u0, u1);
                aSH[j][half + 1] = prmt7632(u2, u3);
                aSL[j][half + 0] =
                    cvt_bf2(v0 - __uint_as_float(u0 & 0xFFFF0000u),
                            v1 - __uint_as_float(u1 & 0xFFFF0000u));
                aSL[j][half + 1] =
                    cvt_bf2(v2 - __uint_as_float(u2 & 0xFFFF0000u),
                            v3 - __uint_as_float(u3 & 0xFFFF0000u));
            }

            // ---- GEMM2: out[16x128] += S(frag, split) @ Zt-as-B(split) ----
#pragma unroll
            for (int j = 0; j < 4; j++) {
#pragma unroll
                for (int nh = 0; nh < 8; nh++) {
                    uint32_t bH2[4], bL2[4];
                    const uint32_t boff = b2off + (uint32_t)(nh * 16 * PT + j * 16) * 2;
                    ldsm_x4(bH2, ztH + boff);
                    ldsm_x4(bL2, ztL + boff);
                    mma16816(oacc[2 * nh], aSH[j], &bH2[0]);
                    mma16816(oacc[2 * nh + 1], aSH[j], &bH2[2]);
                    mma16816(oacc[2 * nh], aSH[j], &bL2[0]);
                    mma16816(oacc[2 * nh + 1], aSH[j], &bL2[2]);
                    mma16816(oacc[2 * nh], aSL[j], &bH2[0]);
                    mma16816(oacc[2 * nh + 1], aSL[j], &bH2[2]);
                }
            }
        }

        // ---- segment flush: rowsum + out partial via atomics ----
        rs0 += __shfl_xor_sync(~0u, rs0, 1);
        rs0 += __shfl_xor_sync(~0u, rs0, 2);
        rs1 += __shfl_xor_sync(~0u, rs1, 1);
        rs1 += __shfl_xor_sync(~0u, rs1, 2);
        if (tq == 0) {
            atomicAdd(&g_rs[n0 + wid * 16 + g], rs0);
            atomicAdd(&g_rs[n0 + wid * 16 + 8 + g], rs1);
        }
        const int r0 = n0 + wid * 16 + g;
#pragma unroll
        for (int o = 0; o < 16; o++) {
            const int col = o * 8 + 2 * tq;
            atomicAdd(&g_outp[r0 * HID + col], oacc[o][0]);
            atomicAdd(&g_outp[r0 * HID + col + 1], oacc[o][1]);
            atomicAdd(&g_outp[(r0 + 8) * HID + col], oacc[o][2]);
            atomicAdd(&g_outp[(r0 + 8) * HID + col + 1], oacc[o][3]);
        }

        gid = segEnd;
    }
}

// ---------------------------------------------------------------------------
// Phase 3 (fused): blocks 0..8191 normalize A (8 float4/thread streaming);
// blocks 8192..8223 compute out = g_outp * inv(rowsum).
// ---------------------------------------------------------------------------
__global__ __launch_bounds__(256) void k_norm(float* __restrict__ A,
                                              float* __restrict__ o) {
    if (blockIdx.x < 8192) {
        const long i0 = (long)blockIdx.x * 2048 + threadIdx.x;
        float4 v[8];
        float inv[8];
#pragma unroll
        for (int j = 0; j < 8; j++) {
            long i = i0 + j * 256;
            v[j] = __ldcs(&((const float4*)A)[i]);
            int r = (int)(i >> 11);
            inv[j] = 1.0f / (g_rs[r] + 1e-6f);
        }
#pragma unroll
        for (int j = 0; j < 8; j++) {
            long i = i0 + j * 256;
            float4 w = v[j];
            w.x *= inv[j]; w.y *= inv[j]; w.z *= inv[j]; w.w *= inv[j];
            __stcs(&((float4*)A)[i], w);
        }
    } else {
        int base = (blockIdx.x - 8192) * 256 * 128 + threadIdx.x;
#pragma unroll
        for (int j = 0; j < 128; j++) {
            int i = base + j * 256;
            int r = i >> 7;
            o[i] = g_outp[i] * (1.0f / (g_rs[r] + 1e-6f));
        }
    }
}

// ---------------------------------------------------------------------------
extern "C" void kernel_launch(void* const* d_in, const int* in_sizes, int n_in,
                              void* d_out, int out_size) {
    const float* X = (const float*)d_in[0];
    const float* W = (const float*)d_in[1];
    float* out = (float*)d_out;
    float* A = out + NN * HID;

    k_gemm_z<<<dim3(NN / 64, HID / 64), 256>>>(X, W);

    cudaFuncSetAttribute(k_pass2, cudaFuncAttributeMaxDynamicSharedMemorySize,
                         SMEM_BYTES);
    k_pass2<<<NCTA, 128, SMEM_BYTES>>>(A);

    k_norm<<<8224, 256>>>(A, out);
}

// round 17
// speedup vs baseline: 1.0271x; 1.0271x over previous
#include <cuda_runtime.h>
#include <cuda_bf16.h>
#include <cstdint>

#define NN 8192
#define IN_DIM 256
#define HID 128
#define PZ 136  // pitch bf16, 128-col tiles (odd 16B stride)
#define PT 72   // pitch bf16, 64-col tiles (odd 16B stride)
#define NCTA 148
#define NTILE 8192  // 64 rowblocks(128r) x 128 coltiles(64c)

// smem element offsets (bf16)
#define ZNH_E 0
#define ZNL_E (128 * PZ)
#define ZT_E(buf, hl) (2 * 128 * PZ + ((buf) * 2 + (hl)) * 128 * PT)  // buf 0..2
#define SMEM_BYTES ((2 * 128 * PZ + 6 * 128 * PT) * 2)  // 180224

// ---------------- device scratch (no cudaMalloc allowed) -------------------
__device__ __nv_bfloat16 g_Zhi[NN * HID];
__device__ __nv_bfloat16 g_Zlo[NN * HID];
__device__ __nv_bfloat16 g_ZThi[(long)HID * NN];
__device__ __nv_bfloat16 g_ZTlo[(long)HID * NN];
__device__ float g_outp[NN * HID];  // atomically accumulated out partial
__device__ float g_rs[NN];          // atomically accumulated rowsum

// ---------------- primitives (baseline PTX, no sm_103a gating) -------------
__device__ __forceinline__ uint32_t smem_u32(const void* p) {
    uint32_t a;
    asm("{ .reg .u64 t; cvta.to.shared.u64 t, %1; cvt.u32.u64 %0, t; }"
        : "=r"(a) : "l"(p));
    return a;
}
__device__ __forceinline__ void ldsm_x4(uint32_t* r, uint32_t addr) {
    asm volatile("ldmatrix.sync.aligned.m8n8.x4.shared.b16 {%0,%1,%2,%3}, [%4];"
                 : "=r"(r[0]), "=r"(r[1]), "=r"(r[2]), "=r"(r[3]) : "r"(addr));
}
__device__ __forceinline__ void ldsm_x4t(uint32_t* r, uint32_t addr) {
    asm volatile("ldmatrix.sync.aligned.m8n8.x4.trans.shared.b16 {%0,%1,%2,%3}, [%4];"
                 : "=r"(r[0]), "=r"(r[1]), "=r"(r[2]), "=r"(r[3]) : "r"(addr));
}
__device__ __forceinline__ void mma16816(float* c, const uint32_t* a,
                                         const uint32_t* b) {
    asm volatile(
        "mma.sync.aligned.m16n8k16.row.col.f32.bf16.bf16.f32 "
        "{%0,%1,%2,%3}, {%4,%5,%6,%7}, {%8,%9}, {%0,%1,%2,%3};"
        : "+f"(c[0]), "+f"(c[1]), "+f"(c[2]), "+f"(c[3])
        : "r"(a[0]), "r"(a[1]), "r"(a[2]), "r"(a[3]), "r"(b[0]), "r"(b[1]));
}
__device__ __forceinline__ void cp16(uint32_t dst, const void* src) {
    asm volatile("cp.async.cg.shared.global [%0], [%1], 16;"
                 :: "r"(dst), "l"(src));
}
#define CP_COMMIT() asm volatile("cp.async.commit_group;")
#define CP_WAIT1() asm volatile("cp.async.wait_group 1;")
#define CP_WAIT0() asm volatile("cp.async.wait_group 0;")
__device__ __forceinline__ void stcs2(float* p, float x, float y) {
    asm volatile("st.global.cs.v2.f32 [%0], {%1,%2};" :: "l"(p), "f"(x), "f"(y));
}
// hi-pack of truncated bf16 pair: d = [v0.top16, v1.top16]
__device__ __forceinline__ uint32_t prmt7632(uint32_t a, uint32_t b) {
    uint32_t d;
    asm("prmt.b32 %0, %1, %2, 0x7632;" : "=r"(d) : "r"(a), "r"(b));
    return d;
}
// lo-pack: {lower=cvt(l0), upper=cvt(l1)}
__device__ __forceinline__ uint32_t cvt_bf2(float l0, float l1) {
    uint32_t d;
    asm("cvt.rn.bf16x2.f32 %0, %1, %2;" : "=r"(d) : "f"(l1), "f"(l0));
    return d;
}

// ---------------------------------------------------------------------------
// Phase 1: Z = X @ W^T (fp32), emit bf16 hi/lo + smem-staged transposed hi/lo.
// Also zeroes g_outp and g_rs (needed before pass2 atomics).
// ---------------------------------------------------------------------------
__global__ __launch_bounds__(256) void k_gemm_z(const float* __restrict__ X,
                                                const float* __restrict__ W) {
    __shared__ __align__(16) float pool[2 * 64 * 33];
    float* Xs = pool;
    float* Ws = pool + 64 * 33;
    const int tid = threadIdx.x;
    const int flatb = blockIdx.y * gridDim.x + blockIdx.x;  // 0..255
    {
        float4 z4 = make_float4(0.f, 0.f, 0.f, 0.f);
        float4* op4 = (float4*)g_outp + (flatb * 256 + tid) * 4;
#pragma unroll
        for (int j = 0; j < 4; j++) op4[j] = z4;
        if (flatb < 32) g_rs[flatb * 256 + tid] = 0.0f;
    }
    const int tx = tid & 15, ty = tid >> 4;
    const int row0 = blockIdx.x * 64;
    const int col0 = blockIdx.y * 64;
    float acc[4][4] = {};

    for (int k0 = 0; k0 < IN_DIM; k0 += 32) {
        for (int idx = tid; idx < 64 * 32; idx += 256) {
            int r = idx >> 5, c = idx & 31;
            Xs[r * 33 + c] = X[(row0 + r) * IN_DIM + k0 + c];
            Ws[r * 33 + c] = W[(col0 + r) * IN_DIM + k0 + c];
        }
        __syncthreads();
#pragma unroll 8
        for (int k = 0; k < 32; k++) {
            float a[4], b[4];
#pragma unroll
            for (int i = 0; i < 4; i++) a[i] = Xs[(ty * 4 + i) * 33 + k];
#pragma unroll
            for (int j = 0; j < 4; j++) b[j] = Ws[(tx * 4 + j) * 33 + k];
#pragma unroll
            for (int i = 0; i < 4; i++)
#pragma unroll
                for (int j = 0; j < 4; j++) acc[i][j] = fmaf(a[i], b[j], acc[i][j]);
        }
        __syncthreads();
    }

    __nv_bfloat16 h4[4][4], l4[4][4];
#pragma unroll
    for (int i = 0; i < 4; i++)
#pragma unroll
        for (int j = 0; j < 4; j++) {
            int r = row0 + ty * 4 + i, c = col0 + tx * 4 + j;
            float v = acc[i][j];
            __nv_bfloat16 h = __float2bfloat16(v);
            __nv_bfloat16 l = __float2bfloat16(v - __bfloat162float(h));
            h4[i][j] = h; l4[i][j] = l;
            g_Zhi[r * HID + c] = h;
            g_Zlo[r * HID + c] = l;
        }

    __nv_bfloat16* tb = (__nv_bfloat16*)pool;
#pragma unroll
    for (int pass = 0; pass < 2; pass++) {
        __syncthreads();
#pragma unroll
        for (int i = 0; i < 4; i++)
#pragma unroll
            for (int j = 0; j < 4; j++)
                tb[(tx * 4 + j) * 72 + ty * 4 + i] = pass ? l4[i][j] : h4[i][j];
        __syncthreads();
        __nv_bfloat16* gp = pass ? g_ZTlo : g_ZThi;
#pragma unroll
        for (int k = 0; k < 2; k++) {
            int idx = tid + k * 256;
            int c_loc = idx >> 3;
            int r8 = (idx & 7) * 8;
            *(uint4*)&gp[(long)(col0 + c_loc) * NN + row0 + r8] =
                *(uint4*)&tb[c_loc * 72 + r8];
        }
    }
}

// ---------------------------------------------------------------------------
__device__ __forceinline__ void copy_tile_z(__nv_bfloat16* __restrict__ dst,
                                            const __nv_bfloat16* __restrict__ src,
                                            int tid) {
#pragma unroll
    for (int i = 0; i < 8; i++) {
        int idx = tid + i * 256;
        int row = idx >> 4;
        int c8 = (idx & 15) * 8;
        *(uint4*)&dst[row * PZ + c8] = *(const uint4*)&src[(long)row * HID + c8];
    }
}

// issue async copy of one 128x64 Zt tile pair (hi+lo) into buffer buf (0..2)
__device__ __forceinline__ void issue_zt(uint32_t smb, int buf, int m0, int tid) {
    const __nv_bfloat16* gh = g_ZThi + m0;
    const __nv_bfloat16* gl = g_ZTlo + m0;
    const uint32_t dH = smb + ZT_E(buf, 0) * 2;
    const uint32_t dL = smb + ZT_E(buf, 1) * 2;
#pragma unroll
    for (int i = 0; i < 4; i++) {
        int idx = tid + i * 256;
        int row = idx >> 3;
        int c8 = (idx & 7) * 8;
        uint32_t so = (uint32_t)(row * PT + c8) * 2;
        long go = (long)row * NN + c8;
        cp16(dH + so, gh + go);
        cp16(dL + so, gl + go);
    }
}

// ---------------------------------------------------------------------------
// Phase 2: persistent balanced scheduling over 8192 (rowblock128, coltile64)
// units; 148 CTAs x 256 threads. Register-resident S (FA2): warp owns 16
// S-rows x 64-col tile. Cheap trunc-split epilogue (prmt/cvt).
// ---------------------------------------------------------------------------
__global__ __launch_bounds__(256, 1) void k_pass2(float* __restrict__ A) {
    extern __shared__ __nv_bfloat16 sm[];
    const uint32_t smb = smem_u32(sm);
    const int tid = threadIdx.x;
    const int wid = tid >> 5, lane = tid & 31;
    const int g = lane >> 2, tq = lane & 3;
    const int l15 = lane & 15;
    const int hi8 = (lane >> 4) * 8;

    int gid = (int)(((long)blockIdx.x * NTILE) / NCTA);
    const int gend = (int)(((long)(blockIdx.x + 1) * NTILE) / NCTA);

    const uint32_t a1H = smb + (ZNH_E + (wid * 16 + l15) * PZ + hi8) * 2;
    const uint32_t a1L = smb + (ZNL_E + (wid * 16 + l15) * PZ + hi8) * 2;
    const uint32_t b2off =
        (uint32_t)((((lane & 7) + ((lane >> 4) & 1) * 8) * PT +
                    ((lane >> 3) & 1) * 8) * 2);

    while (gid < gend) {
        const int rb = gid >> 7;
        const int segEnd = min(gend, (rb + 1) << 7);
        const int segLen = segEnd - gid;
        const int n0 = rb << 7;

        __syncthreads();  // prior segment fully done with smem

        copy_tile_z(sm + ZNH_E, g_Zhi + (long)n0 * HID, tid);
        copy_tile_z(sm + ZNL_E, g_Zlo + (long)n0 * HID, tid);
        issue_zt(smb, 0, (gid & 127) * 64, tid);
        CP_COMMIT();
        if (segLen > 1) {
            issue_zt(smb, 1, ((gid + 1) & 127) * 64, tid);
            CP_COMMIT();
        }
        __syncthreads();

        uint32_t rAH[8][4], rAL[8][4];
#pragma unroll
        for (int k8 = 0; k8 < 8; k8++) {
            ldsm_x4(rAH[k8], a1H + (k8 * 16) * 2);
            ldsm_x4(rAL[k8], a1L + (k8 * 16) * 2);
        }

        float oacc[16][4] = {};
        float rs0 = 0.0f, rs1 = 0.0f;

        for (int i = 0; i < segLen; i++) {
            const int cur = i % 3;
            const int m0 = ((gid + i) & 127) * 64;
            if (i + 1 < segLen) CP_WAIT1(); else CP_WAIT0();
            __syncthreads();  // Zt[cur] ready; slot (i+2)%3 free
            if (i + 2 < segLen) {
                issue_zt(smb, (i + 2) % 3, ((gid + i + 2) & 127) * 64, tid);
                CP_COMMIT();
            }

            const uint32_t ztH = smb + ZT_E(cur, 0) * 2;
            const uint32_t ztL = smb + ZT_E(cur, 1) * 2;
            const uint32_t b1H = ztH + (uint32_t)(l15 * PT + hi8) * 2;
            const uint32_t b1L = ztL + (uint32_t)(l15 * PT + hi8) * 2;

            // ---- GEMM1: S[16x64] = Zn(split) @ Zt(split) ----
            float cacc[8][4] = {};
#pragma unroll
            for (int k8 = 0; k8 < 8; k8++) {
                uint32_t bH[4][4], bL[4][4];
#pragma unroll
                for (int nc = 0; nc < 4; nc++) {
                    ldsm_x4t(bH[nc], b1H + (uint32_t)(k8 * 16 * PT + nc * 16) * 2);
                    ldsm_x4t(bL[nc], b1L + (uint32_t)(k8 * 16 * PT + nc * 16) * 2);
                }
#pragma unroll
                for (int nc = 0; nc < 4; nc++) {
                    mma16816(cacc[2 * nc], rAH[k8], &bH[nc][0]);
                    mma16816(cacc[2 * nc + 1], rAH[k8], &bH[nc][2]);
                    mma16816(cacc[2 * nc], rAH[k8], &bL[nc][0]);
                    mma16816(cacc[2 * nc + 1], rAH[k8], &bL[nc][2]);
                    mma16816(cacc[2 * nc], rAL[k8], &bH[nc][0]);
                    mma16816(cacc[2 * nc + 1], rAL[k8], &bH[nc][2]);
                }
            }

            // ---- epilogue: relu, rowsum, A store, cheap trunc-split pack ----
            uint32_t aSH[4][4], aSL[4][4];
#pragma unroll
            for (int nf = 0; nf < 8; nf++) {
                float* c = cacc[nf];
                float v0 = fmaxf(c[0], 0.f), v1 = fmaxf(c[1], 0.f);
                float v2 = fmaxf(c[2], 0.f), v3 = fmaxf(c[3], 0.f);
                rs0 += v0 + v1;
                rs1 += v2 + v3;
                const int lr = wid * 16 + g;
                const int lc = nf * 8 + 2 * tq;
                stcs2(&A[(long)(n0 + lr) * NN + m0 + lc], v0, v1);
                stcs2(&A[(long)(n0 + lr + 8) * NN + m0 + lc], v2, v3);
                uint32_t u0 = __float_as_uint(v0), u1 = __float_as_uint(v1);
                uint32_t u2 = __float_as_uint(v2), u3 = __float_as_uint(v3);
                const int j = nf >> 1, half = (nf & 1) * 2;
                aSH[j][half + 0] = prmt7632(u0, u1);
                aSH[j][half + 1] = prmt7632(u2, u3);
                aSL[j][half + 0] =
                    cvt_bf2(v0 - __uint_as_float(u0 & 0xFFFF0000u),
                            v1 - __uint_as_float(u1 & 0xFFFF0000u));
                aSL[j][half + 1] =
                    cvt_bf2(v2 - __uint_as_float(u2 & 0xFFFF0000u),
                            v3 - __uint_as_float(u3 & 0xFFFF0000u));
            }

            // ---- GEMM2: out[16x128] += S(frag, split) @ Zt-as-B(split) ----
#pragma unroll
            for (int j = 0; j < 4; j++) {
#pragma unroll
                for (int nh = 0; nh < 8; nh++) {
                    uint32_t bH2[4], bL2[4];
                    const uint32_t boff = b2off + (uint32_t)(nh * 16 * PT + j * 16) * 2;
                    ldsm_x4(bH2, ztH + boff);
                    ldsm_x4(bL2, ztL + boff);
                    mma16816(oacc[2 * nh], aSH[j], &bH2[0]);
                    mma16816(oacc[2 * nh + 1], aSH[j], &bH2[2]);
                    mma16816(oacc[2 * nh], aSH[j], &bL2[0]);
                    mma16816(oacc[2 * nh + 1], aSH[j], &bL2[2]);
                    mma16816(oacc[2 * nh], aSL[j], &bH2[0]);
                    mma16816(oacc[2 * nh + 1], aSL[j], &bH2[2]);
                }
            }
        }

        // ---- segment flush: rowsum + out partial via atomics ----
        rs0 += __shfl_xor_sync(~0u, rs0, 1);
        rs0 += __shfl_xor_sync(~0u, rs0, 2);
        rs1 += __shfl_xor_sync(~0u, rs1, 1);
        rs1 += __shfl_xor_sync(~0u, rs1, 2);
        if (tq == 0) {
            atomicAdd(&g_rs[n0 + wid * 16 + g], rs0);
            atomicAdd(&g_rs[n0 + wid * 16 + 8 + g], rs1);
        }
        const int r0 = n0 + wid * 16 + g;
#pragma unroll
        for (int o = 0; o < 16; o++) {
            const int col = o * 8 + 2 * tq;
            atomicAdd(&g_outp[r0 * HID + col], oacc[o][0]);
            atomicAdd(&g_outp[r0 * HID + col + 1], oacc[o][1]);
            atomicAdd(&g_outp[(r0 + 8) * HID + col], oacc[o][2]);
            atomicAdd(&g_outp[(r0 + 8) * HID + col + 1], oacc[o][3]);
        }

        gid = segEnd;
    }
}

// ---------------------------------------------------------------------------
// Phase 3 (fused): blocks 0..8191 normalize A (8 float4/thread streaming);
// blocks 8192..8223 compute out = g_outp * inv(rowsum).
// ---------------------------------------------------------------------------
__global__ __launch_bounds__(256) void k_norm(float* __restrict__ A,
                                              float* __restrict__ o) {
    if (blockIdx.x < 8192) {
        const long i0 = (long)blockIdx.x * 2048 + threadIdx.x;
        float4 v[8];
        float inv[8];
#pragma unroll
        for (int j = 0; j < 8; j++) {
            long i = i0 + j * 256;
            v[j] = __ldcs(&((const float4*)A)[i]);
            int r = (int)(i >> 11);
            inv[j] = 1.0f / (g_rs[r] + 1e-6f);
        }
#pragma unroll
        for (int j = 0; j < 8; j++) {
            long i = i0 + j * 256;
            float4 w = v[j];
            w.x *= inv[j]; w.y *= inv[j]; w.z *= inv[j]; w.w *= inv[j];
            __stcs(&((float4*)A)[i], w);
        }
    } else {
        int base = (blockIdx.x - 8192) * 256 * 128 + threadIdx.x;
#pragma unroll
        for (int j = 0; j < 128; j++) {
            int i = base + j * 256;
            int r = i >> 7;
            o[i] = g_outp[i] * (1.0f / (g_rs[r] + 1e-6f));
        }
    }
}

// ---------------------------------------------------------------------------
extern "C" void kernel_launch(void* const* d_in, const int* in_sizes, int n_in,
                              void* d_out, int out_size) {
    const float* X = (const float*)d_in[0];
    const float* W = (const float*)d_in[1];
    float* out = (float*)d_out;
    float* A = out + NN * HID;

    k_gemm_z<<<dim3(NN / 64, HID / 64), 256>>>(X, W);

    cudaFuncSetAttribute(k_pass2, cudaFuncAttributeMaxDynamicSharedMemorySize,
                         SMEM_BYTES);
    k_pass2<<<NCTA, 256, SMEM_BYTES>>>(A);

    k_norm<<<8224, 256>>>(A, out);
}